// round 12
// baseline (speedup 1.0000x reference)
#include <cuda_runtime.h>
#include <stdint.h>

#define BB 1024
#define TT 1024
#define KK 48
#define START_TAG 46
#define STOP_TAG 47
#define NEGV (-10000.0f)
#define PADV (-3.0e38f)
#define NT 96                  // one sequence per block: 2 threads per 'next' tag

// scratch, layout [seq][tag][t]:
// g_fv[t] = fv AFTER step t;  g_m[t] = pre-feat max of step t
__device__ __align__(16) float g_fv[(size_t)BB * KK * TT];
__device__ __align__(16) float g_m[(size_t)BB * KK * TT];

// monotone float -> ordered signed int (exact for all non-NaN floats)
__device__ __forceinline__ int fkey(float f) {
    int i = __float_as_int(f);
    return (i >= 0) ? i : (i ^ 0x7fffffff);
}

// exact argmax over 48 candidates (terminal only): lane l holds index l (sa)
// and 32+l (sb, PADV for l>=16). Ties -> lowest index.
__device__ __forceinline__ int argmax48(float sa, float sb, float* bout) {
    int ka = fkey(sa), kb = fkey(sb);
    int v = (ka > kb) ? ka : kb;
    int m;
    asm("redux.sync.max.s32 %0, %1, 0xffffffff;" : "=r"(m) : "r"(v));
    unsigned ba = __ballot_sync(0xffffffffu, ka == m);
    unsigned bb = __ballot_sync(0xffffffffu, kb == m);
    int idx = ba ? (__ffs((int)ba) - 1) : (31 + __ffs((int)bb));
    int mi = (m >= 0) ? m : (m ^ 0x7fffffff);
    *bout = __int_as_float(mi);
    return idx;
}

__global__ __launch_bounds__(NT)
void viterbi_kernel(const float* __restrict__ feats,
                    const float* __restrict__ trans,
                    float* __restrict__ out)
{
    __shared__ __align__(16) float fv_sh[2][KK];
    __shared__ __align__(16) float trans_sh[KK * KK];
    __shared__ uint8_t path_sh[TT];

    const int tid = threadIdx.x;
    const int n   = tid >> 1;        // 'next' tag 0..47
    const int c   = tid & 1;         // half: prevs [c*24, c*24+24)
    const int seq = blockIdx.x;      // grid == BB

    // stage transitions into smem (used only by backtrack)
    for (int i2 = tid; i2 < KK * KK; i2 += NT) trans_sh[i2] = trans[i2];

    // this thread's 24 transition entries live in registers all T steps
    float tr[24];
#pragma unroll
    for (int k = 0; k < 24; k++) tr[k] = trans[n * KK + c * 24 + k];

    if (c == 0) fv_sh[0][n] = (n == START_TAG) ? 0.0f : NEGV;
    __syncthreads();

    const float* fbase = feats + (size_t)seq * TT * KK + n;
    // 2-deep feat prefetch
    float f_cur = fbase[0];
    float f_nxt = fbase[KK];
    float* sptr = g_fv + ((size_t)seq * KK + n) * TT;   // fv store cursor (c==0)
    float* mptr = g_m  + ((size_t)seq * KK + n) * TT;   // m  store cursor (c==1)

    // ---------------- forward pass: max-only (R10-proven loop) ----------------
    int buf = 0;
    float vb0, vb1, vb2, vb3;       // c==0: fv values
    float mb0, mb1, mb2, mb3;       // c==1: pre-feat maxima
    for (int t = 0; t < TT; t += 4) {
#pragma unroll
        for (int k = 0; k < 4; k++) {
            const int tt = t + k;
            float feat = f_cur;
            f_cur = f_nxt;
            int tn = (tt + 2 < TT) ? (tt + 2) : (TT - 1);   // clamped prefetch
            f_nxt = fbase[(size_t)tn * KK];

            const float4* fvr =
                reinterpret_cast<const float4*>(&fv_sh[buf][c * 24]);
            float4 v0 = fvr[0];
            float b0 = v0.x + tr[0], b1 = v0.y + tr[1];
            float b2 = v0.z + tr[2], b3 = v0.w + tr[3];
#pragma unroll
            for (int q = 1; q < 6; q++) {
                float4 w = fvr[q];
                b0 = fmaxf(b0, w.x + tr[4 * q + 0]);
                b1 = fmaxf(b1, w.y + tr[4 * q + 1]);
                b2 = fmaxf(b2, w.z + tr[4 * q + 2]);
                b3 = fmaxf(b3, w.w + tr[4 * q + 3]);
            }
            float b = fmaxf(fmaxf(b0, b1), fmaxf(b2, b3));
            b = fmaxf(b, __shfl_xor_sync(0xffffffffu, b, 1)); // both halves get b
            float newfv = b + feat;
            if (c == 0) {
                fv_sh[buf ^ 1][n] = newfv;     // critical path: STS only
                if (k == 0) vb0 = newfv;
                else if (k == 1) vb1 = newfv;
                else if (k == 2) vb2 = newfv;
                else vb3 = newfv;
            } else {
                if (k == 0) mb0 = b;           // pre-feat max for backtrack
                else if (k == 1) mb1 = b;
                else if (k == 2) mb2 = b;
                else mb3 = b;
            }
            __syncthreads();
            buf ^= 1;
        }
        if (c == 0) {
            *reinterpret_cast<float4*>(sptr) = make_float4(vb0, vb1, vb2, vb3);
        } else {
            *reinterpret_cast<float4*>(mptr) = make_float4(mb0, mb1, mb2, mb3);
        }
        sptr += 4; mptr += 4;
    }

    // ---------------- terminal + equality-scan backtrack (warp 0) -------------
    if (tid < 32) {
        const int l = tid;
        float fa = fv_sh[buf][l];
        float fb = (l < 16) ? fv_sh[buf][32 + l] : 0.0f;
        float sa = fa + trans_sh[STOP_TAG * KK + l];
        float sb = (l < 16) ? (fb + trans_sh[STOP_TAG * KK + 32 + l]) : PADV;
        float best;
        int tag = argmax48(sa, sb, &best);
        if (l == 0) out[seq] = best;

        const float* rbA = g_fv + ((size_t)seq * KK + l) * TT;
        const float* rbB = g_fv + ((size_t)seq * KK + 32 + l) * TT;
        const float* rmA = g_m  + ((size_t)seq * KK + l) * TT;
        const float* rmB = g_m  + ((size_t)seq * KK + 32 + l) * TT;

        // 3-deep prefetch: step t needs fv_after[t-1] and m[t]
        float a0 = rbA[TT - 2], e0 = (l < 16) ? rbB[TT - 2] : 0.0f;
        float p0 = rmA[TT - 1], q0 = (l < 16) ? rmB[TT - 1] : 0.0f;
        float a1 = rbA[TT - 3], e1 = (l < 16) ? rbB[TT - 3] : 0.0f;
        float p1 = rmA[TT - 2], q1 = (l < 16) ? rmB[TT - 2] : 0.0f;
        float a2 = rbA[TT - 4], e2 = (l < 16) ? rbB[TT - 4] : 0.0f;
        float p2 = rmA[TT - 3], q2 = (l < 16) ? rmB[TT - 3] : 0.0f;

#define BT_STEP(T_, AA, EE, PP, QQ, PF)                                       \
        {                                                                     \
            if (l == 0) path_sh[(T_)] = (uint8_t)tag;                         \
            float mAv = __shfl_sync(0xffffffffu, PP, tag & 31);               \
            float mBv = __shfl_sync(0xffffffffu, QQ, tag & 31);               \
            float mval = (tag < 32) ? mAv : mBv;                              \
            float trA = trans_sh[tag * KK + l];                               \
            float trB = trans_sh[tag * KK + ((l < 16) ? (32 + l) : l)];       \
            unsigned ba = __ballot_sync(0xffffffffu, AA + trA == mval);       \
            unsigned bb = __ballot_sync(0xffffffffu,                          \
                                        (l < 16) && (EE + trB == mval));      \
            int rpf = ((PF) < 1) ? 1 : (PF);                                  \
            AA = rbA[rpf - 1];  EE = (l < 16) ? rbB[rpf - 1] : 0.0f;          \
            PP = rmA[rpf];      QQ = (l < 16) ? rmB[rpf] : 0.0f;              \
            tag = ba ? (__ffs((int)ba) - 1) : (31 + __ffs((int)bb));          \
        }

        for (int t = TT - 1; t >= 3; t -= 3) {   // steps TT-1 .. 1
            BT_STEP(t,     a0, e0, p0, q0, t - 3)
            BT_STEP(t - 1, a1, e1, p1, q1, t - 4)
            BT_STEP(t - 2, a2, e2, p2, q2, t - 5)
        }
        if (l == 0) path_sh[0] = (uint8_t)tag;
#undef BT_STEP
    }
    __syncthreads();

    // ---------------- coalesced path dump ----------------
    float* pout = out + BB + (size_t)seq * TT;
    for (int t = tid; t < TT; t += NT) pout[t] = (float)path_sh[t];
}

extern "C" void kernel_launch(void* const* d_in, const int* in_sizes, int n_in,
                              void* d_out, int out_size) {
    (void)in_sizes; (void)n_in; (void)out_size;
    const float* feats = (const float*)d_in[0];
    const float* trans = (const float*)d_in[1];
    float* out = (float*)d_out;
    viterbi_kernel<<<BB, NT>>>(feats, trans, out);
}

// round 15
// speedup vs baseline: 1.6626x; 1.6626x over previous
#include <cuda_runtime.h>
#include <stdint.h>

#define BB 1024
#define TT 1024
#define KK 48
#define START_TAG 46
#define STOP_TAG 47
#define NEGV (-10000.0f)
#define PADV (-3.0e38f)
#define NT 96                  // one sequence per block: 2 threads per 'next' tag

// forward-variable scratch: [t][seq][tag] (row t = fv BEFORE step t), +1 pad row
__device__ __align__(16) float g_fv[(size_t)(TT + 1) * BB * KK];

// monotone float -> ordered signed int (exact for all non-NaN floats)
__device__ __forceinline__ int fkey(float f) {
    int i = __float_as_int(f);
    return (i >= 0) ? i : (i ^ 0x7fffffff);
}

// exact argmax over 48 candidates: lane l holds index l (sa) and 32+l (sb, PADV
// for l>=16). Ties -> lowest index (matches jnp.argmax first occurrence).
__device__ __forceinline__ int argmax48(float sa, float sb, float* bout) {
    int ka = fkey(sa), kb = fkey(sb);
    int v = (ka > kb) ? ka : kb;
    int m;
    asm("redux.sync.max.s32 %0, %1, 0xffffffff;" : "=r"(m) : "r"(v));
    unsigned ba = __ballot_sync(0xffffffffu, ka == m);
    unsigned bb = __ballot_sync(0xffffffffu, kb == m);
    int idx = ba ? (__ffs((int)ba) - 1) : (31 + __ffs((int)bb));
    int mi = (m >= 0) ? m : (m ^ 0x7fffffff);
    *bout = __int_as_float(mi);
    return idx;
}

__global__ __launch_bounds__(NT)
void viterbi_kernel(const float* __restrict__ feats,
                    const float* __restrict__ trans,
                    float* __restrict__ out)
{
    __shared__ __align__(16) float fv_sh[2][KK];
    __shared__ __align__(16) float trans_sh[KK * KK];
    __shared__ __align__(16) float win_sh[8][KK];   // 8-step store staging
    __shared__ uint8_t path_sh[TT];

    const int tid = threadIdx.x;
    const int n   = tid >> 1;        // 'next' tag 0..47
    const int c   = tid & 1;         // half: prevs [c*24, c*24+24)
    const int seq = blockIdx.x;      // grid == BB

    // stage transitions into smem (used only by backtrack)
    for (int i2 = tid; i2 < KK * KK; i2 += NT) trans_sh[i2] = trans[i2];

    // this thread's 24 transition entries live in registers all T steps
    float tr[24];
#pragma unroll
    for (int k = 0; k < 24; k++) tr[k] = trans[n * KK + c * 24 + k];

    if (c == 0) fv_sh[0][n] = (n == START_TAG) ? 0.0f : NEGV;
    __syncthreads();

    const float* fbase = feats + (size_t)seq * TT * KK + n;
    // 2-deep feat prefetch
    float f_cur = fbase[0];
    float f_nxt = fbase[KK];
    const size_t RSTR = (size_t)BB * KK;

    // flush indexing: 96 threads x one float4 = 8 rows x 48 floats
    const int frow = tid / 12;        // 0..7
    const int fcol = tid % 12;        // float4 index within row

    // ---------------- forward pass: max-only ----------------
    int buf = 0;
    for (int t0 = 0; t0 < TT; t0 += 8) {
#pragma unroll
        for (int k = 0; k < 8; k++) {
            const int tt = t0 + k;
            float feat = f_cur;
            f_cur = f_nxt;
            int tn = (tt + 2 < TT) ? (tt + 2) : (TT - 1);   // clamped prefetch
            f_nxt = fbase[(size_t)tn * KK];

            const float4* fvr =
                reinterpret_cast<const float4*>(&fv_sh[buf][c * 24]);
            float4 v0 = fvr[0];
            float b0 = v0.x + tr[0], b1 = v0.y + tr[1];
            float b2 = v0.z + tr[2], b3 = v0.w + tr[3];
#pragma unroll
            for (int q = 1; q < 6; q++) {
                float4 w = fvr[q];
                b0 = fmaxf(b0, w.x + tr[4 * q + 0]);
                b1 = fmaxf(b1, w.y + tr[4 * q + 1]);
                b2 = fmaxf(b2, w.z + tr[4 * q + 2]);
                b3 = fmaxf(b3, w.w + tr[4 * q + 3]);
            }
            float b = fmaxf(fmaxf(b0, b1), fmaxf(b2, b3));
            b = fmaxf(b, __shfl_xor_sync(0xffffffffu, b, 1));  // combine halves
            float newfv = b + feat;
            if (c == 0) {
                fv_sh[buf ^ 1][n] = newfv;     // critical path
                win_sh[k][n] = newfv;          // staging (off-path)
            }
            __syncthreads();
            buf ^= 1;
        }
        // coalesced flush: rows t0+1 .. t0+8 of [t][seq][tag]
        {
            float4 v = reinterpret_cast<const float4*>(&win_sh[frow][0])[fcol];
            float* dst = g_fv + (size_t)(t0 + 1 + frow) * RSTR
                       + (size_t)seq * KK + fcol * 4;
            *reinterpret_cast<float4*>(dst) = v;
        }
        __syncthreads();   // protect win_sh reuse by next window
    }

    // ---------------- terminal + backtrack (warp 0) ----------------
    if (tid < 32) {
        const int l = tid;
        float fa = fv_sh[buf][l];
        float fb = (l < 16) ? fv_sh[buf][32 + l] : 0.0f;
        float sa = fa + trans_sh[STOP_TAG * KK + l];
        float sb = (l < 16) ? (fb + trans_sh[STOP_TAG * KK + 32 + l]) : PADV;
        float best;
        int tag = argmax48(sa, sb, &best);
        if (l == 0) out[seq] = best;

        const float* rowbase = g_fv + (size_t)seq * KK;
        // 3-deep register prefetch of fv rows hides DRAM/L2 latency
        float a0 = rowbase[(size_t)(TT - 1) * RSTR + l];
        float e0 = (l < 16) ? rowbase[(size_t)(TT - 1) * RSTR + 32 + l] : 0.0f;
        float a1 = rowbase[(size_t)(TT - 2) * RSTR + l];
        float e1 = (l < 16) ? rowbase[(size_t)(TT - 2) * RSTR + 32 + l] : 0.0f;
        float a2 = rowbase[(size_t)(TT - 3) * RSTR + l];
        float e2 = (l < 16) ? rowbase[(size_t)(TT - 3) * RSTR + 32 + l] : 0.0f;

#define BT_STEP(T_, AA, EE, PF)                                              \
        {                                                                    \
            if (l == 0) path_sh[(T_)] = (uint8_t)tag;                        \
            float s_a = AA + trans_sh[tag * KK + l];                         \
            float s_b = (l < 16) ? (EE + trans_sh[tag * KK + 32 + l]) : PADV;\
            int rpf = ((PF) < 1) ? 1 : (PF);                                 \
            AA = rowbase[(size_t)rpf * RSTR + l];                            \
            EE = (l < 16) ? rowbase[(size_t)rpf * RSTR + 32 + l] : 0.0f;     \
            float bv;                                                        \
            tag = argmax48(s_a, s_b, &bv);                                   \
        }

        for (int t = TT - 1; t >= 3; t -= 3) {   // 1023 steps, divisible by 3
            BT_STEP(t,     a0, e0, t - 3)
            BT_STEP(t - 1, a1, e1, t - 4)
            BT_STEP(t - 2, a2, e2, t - 5)
        }
        if (l == 0) path_sh[0] = (uint8_t)tag;
#undef BT_STEP
    }
    __syncthreads();

    // ---------------- coalesced path dump ----------------
    float* pout = out + BB + (size_t)seq * TT;
    for (int t = tid; t < TT; t += NT) pout[t] = (float)path_sh[t];
}

extern "C" void kernel_launch(void* const* d_in, const int* in_sizes, int n_in,
                              void* d_out, int out_size) {
    (void)in_sizes; (void)n_in; (void)out_size;
    const float* feats = (const float*)d_in[0];
    const float* trans = (const float*)d_in[1];
    float* out = (float*)d_out;
    viterbi_kernel<<<BB, NT>>>(feats, trans, out);
}

// round 16
// speedup vs baseline: 1.7587x; 1.0579x over previous
#include <cuda_runtime.h>
#include <stdint.h>

#define BB 1024
#define TT 1024
#define KK 48
#define START_TAG 46
#define STOP_TAG 47
#define NEGV (-10000.0f)
#define PADV (-3.0e38f)
#define NT 96                  // one sequence per block: 2 threads per 'next' tag

// forward-variable scratch: [t][seq][tag] (row t = fv BEFORE step t), +1 pad row
__device__ __align__(16) float g_fv[(size_t)(TT + 1) * BB * KK];

// monotone float -> ordered signed int (exact for all non-NaN floats)
__device__ __forceinline__ int fkey(float f) {
    int i = __float_as_int(f);
    return (i >= 0) ? i : (i ^ 0x7fffffff);
}

// exact argmax over 48 candidates: lane l holds index l (sa) and 32+l (sb, PADV
// for l>=16). Ties -> lowest index (matches jnp.argmax first occurrence).
__device__ __forceinline__ int argmax48(float sa, float sb, float* bout) {
    int ka = fkey(sa), kb = fkey(sb);
    int v = (ka > kb) ? ka : kb;
    int m;
    asm("redux.sync.max.s32 %0, %1, 0xffffffff;" : "=r"(m) : "r"(v));
    unsigned ba = __ballot_sync(0xffffffffu, ka == m);
    unsigned bb = __ballot_sync(0xffffffffu, kb == m);
    int idx = ba ? (__ffs((int)ba) - 1) : (31 + __ffs((int)bb));
    int mi = (m >= 0) ? m : (m ^ 0x7fffffff);
    *bout = __int_as_float(mi);
    return idx;
}

__global__ __launch_bounds__(NT)
void viterbi_kernel(const float* __restrict__ feats,
                    const float* __restrict__ trans,
                    float* __restrict__ out)
{
    __shared__ __align__(16) float fv_sh[2][KK];
    __shared__ __align__(16) float trans_sh[KK * KK];
    __shared__ __align__(16) float win_sh[8][KK];        // 8-step fv staging
    __shared__ __align__(16) float feat_sh[2][8][KK];    // 8-step feat staging
    __shared__ uint8_t path_sh[TT];

    const int tid = threadIdx.x;
    const int n   = tid >> 1;        // 'next' tag 0..47
    const int c   = tid & 1;         // half: prevs [c*24, c*24+24)
    const int seq = blockIdx.x;      // grid == BB

    // stage transitions into smem (used only by backtrack)
    for (int i2 = tid; i2 < KK * KK; i2 += NT) trans_sh[i2] = trans[i2];

    // this thread's 24 transition entries live in registers all T steps
    float tr[24];
#pragma unroll
    for (int k = 0; k < 24; k++) tr[k] = trans[n * KK + c * 24 + k];

    const float* fseq = feats + (size_t)seq * TT * KK;   // contiguous [t][tag]
    // window 0 feats: one coalesced float4 per thread (384 floats)
    {
        float4 v = *reinterpret_cast<const float4*>(fseq + tid * 4);
        reinterpret_cast<float4*>(&feat_sh[0][0][0])[tid] = v;
    }
    if (c == 0) fv_sh[0][n] = (n == START_TAG) ? 0.0f : NEGV;
    __syncthreads();

    const size_t RSTR = (size_t)BB * KK;
    // flush indexing: 96 threads x one float4 = 8 rows x 48 floats
    const int frow = tid / 12;        // 0..7
    const int fcol = tid % 12;        // float4 index within row

    // ---------------- forward pass: max-only ----------------
    int buf = 0, fb = 0;
    for (int t0 = 0; t0 < TT; t0 += 8) {
        // prefetch next window's feats (clamped: last window reloads itself)
        const int tnx = (t0 + 8 < TT) ? (t0 + 8) : t0;
        float4 nf4 = *reinterpret_cast<const float4*>(fseq + (size_t)tnx * KK
                                                      + tid * 4);
#pragma unroll
        for (int k = 0; k < 8; k++) {
            float feat = feat_sh[fb][k][n];

            const float4* fvr =
                reinterpret_cast<const float4*>(&fv_sh[buf][c * 24]);
            float4 v0 = fvr[0];
            float b0 = v0.x + tr[0], b1 = v0.y + tr[1];
            float b2 = v0.z + tr[2], b3 = v0.w + tr[3];
#pragma unroll
            for (int q = 1; q < 6; q++) {
                float4 w = fvr[q];
                b0 = fmaxf(b0, w.x + tr[4 * q + 0]);
                b1 = fmaxf(b1, w.y + tr[4 * q + 1]);
                b2 = fmaxf(b2, w.z + tr[4 * q + 2]);
                b3 = fmaxf(b3, w.w + tr[4 * q + 3]);
            }
            float b = fmaxf(fmaxf(b0, b1), fmaxf(b2, b3));
            b = fmaxf(b, __shfl_xor_sync(0xffffffffu, b, 1));  // combine halves
            float newfv = b + feat;
            if (c == 0) {
                fv_sh[buf ^ 1][n] = newfv;     // critical path: one STS
            } else {
                win_sh[k][n] = newfv;          // staging on the idle half
            }
            __syncthreads();
            buf ^= 1;
        }
        // stage next window's feats + coalesced g_fv flush
        reinterpret_cast<float4*>(&feat_sh[fb ^ 1][0][0])[tid] = nf4;
        {
            float4 v = reinterpret_cast<const float4*>(&win_sh[frow][0])[fcol];
            float* dst = g_fv + (size_t)(t0 + 1 + frow) * RSTR
                       + (size_t)seq * KK + fcol * 4;
            *reinterpret_cast<float4*>(dst) = v;
        }
        __syncthreads();   // protects win_sh reuse + feat_sh availability
        fb ^= 1;
    }

    // ---------------- terminal + backtrack (warp 0) ----------------
    if (tid < 32) {
        const int l = tid;
        float fa = fv_sh[buf][l];
        float fb2 = (l < 16) ? fv_sh[buf][32 + l] : 0.0f;
        float sa = fa + trans_sh[STOP_TAG * KK + l];
        float sb = (l < 16) ? (fb2 + trans_sh[STOP_TAG * KK + 32 + l]) : PADV;
        float best;
        int tag = argmax48(sa, sb, &best);
        if (l == 0) out[seq] = best;

        const float* rowbase = g_fv + (size_t)seq * KK;
        // 3-deep register prefetch of fv rows hides DRAM/L2 latency
        float a0 = rowbase[(size_t)(TT - 1) * RSTR + l];
        float e0 = (l < 16) ? rowbase[(size_t)(TT - 1) * RSTR + 32 + l] : 0.0f;
        float a1 = rowbase[(size_t)(TT - 2) * RSTR + l];
        float e1 = (l < 16) ? rowbase[(size_t)(TT - 2) * RSTR + 32 + l] : 0.0f;
        float a2 = rowbase[(size_t)(TT - 3) * RSTR + l];
        float e2 = (l < 16) ? rowbase[(size_t)(TT - 3) * RSTR + 32 + l] : 0.0f;

#define BT_STEP(T_, AA, EE, PF)                                              \
        {                                                                    \
            if (l == 0) path_sh[(T_)] = (uint8_t)tag;                        \
            float s_a = AA + trans_sh[tag * KK + l];                         \
            float s_b = (l < 16) ? (EE + trans_sh[tag * KK + 32 + l]) : PADV;\
            int rpf = ((PF) < 1) ? 1 : (PF);                                 \
            AA = rowbase[(size_t)rpf * RSTR + l];                            \
            EE = (l < 16) ? rowbase[(size_t)rpf * RSTR + 32 + l] : 0.0f;     \
            float bv;                                                        \
            tag = argmax48(s_a, s_b, &bv);                                   \
        }

        for (int t = TT - 1; t >= 3; t -= 3) {   // 1023 steps, divisible by 3
            BT_STEP(t,     a0, e0, t - 3)
            BT_STEP(t - 1, a1, e1, t - 4)
            BT_STEP(t - 2, a2, e2, t - 5)
        }
        if (l == 0) path_sh[0] = (uint8_t)tag;
#undef BT_STEP
    }
    __syncthreads();

    // ---------------- coalesced path dump ----------------
    float* pout = out + BB + (size_t)seq * TT;
    for (int t = tid; t < TT; t += NT) pout[t] = (float)path_sh[t];
}

extern "C" void kernel_launch(void* const* d_in, const int* in_sizes, int n_in,
                              void* d_out, int out_size) {
    (void)in_sizes; (void)n_in; (void)out_size;
    const float* feats = (const float*)d_in[0];
    const float* trans = (const float*)d_in[1];
    float* out = (float*)d_out;
    viterbi_kernel<<<BB, NT>>>(feats, trans, out);
}